// round 2
// baseline (speedup 1.0000x reference)
#include <cuda_runtime.h>
#include <math.h>

#define NROWS 4096
#define DIM   512
#define NMOD  4
#define TILE  64
#define BK    16
// jobs: 4 symmetric pairs * 36 lower-tri tiles + 3 cross pairs * 64 tiles
#define NJOBS 336

// Scratch: normalized matrices (33.5 MB) + 7 Frobenius accumulators.
__device__ float g_norm[(size_t)NMOD * NROWS * DIM];
__device__ float g_acc[7];

__global__ void init_acc_kernel() {
    if (threadIdx.x < 7) g_acc[threadIdx.x] = 0.0f;
}

// One block per row: 128 threads, one float4 each (512 elems).
__global__ void normalize_kernel(const float* __restrict__ in0,
                                 const float* __restrict__ in1,
                                 const float* __restrict__ in2,
                                 const float* __restrict__ in3) {
    int m = blockIdx.y;
    int r = blockIdx.x;
    const float* src = (m == 0 ? in0 : m == 1 ? in1 : m == 2 ? in2 : in3)
                       + (size_t)r * DIM;
    float* dst = g_norm + ((size_t)m * NROWS + r) * DIM;

    int t = threadIdx.x;  // 0..127
    float4 v = ((const float4*)src)[t];
    float ss = v.x * v.x + v.y * v.y + v.z * v.z + v.w * v.w;
    #pragma unroll
    for (int o = 16; o > 0; o >>= 1) ss += __shfl_xor_sync(0xffffffffu, ss, o);
    __shared__ float red[4];
    if ((t & 31) == 0) red[t >> 5] = ss;
    __syncthreads();
    ss = red[0] + red[1] + red[2] + red[3];
    float inv = 1.0f / fmaxf(sqrtf(ss), 1e-12f);  // matches F.normalize eps
    float4 o4 = make_float4(v.x * inv, v.y * inv, v.z * inv, v.w * inv);
    ((float4*)dst)[t] = o4;
}

// Computes a 64x64 tile of C = A^T B (A,B are [4096,512] normalized matrices),
// K-loop over 4096, then sum of squares of the tile -> atomicAdd to g_acc.
__global__ __launch_bounds__(256) void gemm_fro_kernel() {
    __shared__ float As[BK][TILE];
    __shared__ float Bs[BK][TILE];

    int job = blockIdx.x;
    int pa, pb, ti, tj, accIdx;
    float w;
    if (job < 144) {                 // symmetric pairs: lower-triangle tiles
        int p = job / 36;
        int t = job - p * 36;
        int i = 0;
        while (((i + 1) * (i + 2)) / 2 <= t) i++;
        int j = t - (i * (i + 1)) / 2;
        pa = p; pb = p; ti = i; tj = j;
        accIdx = p;                  // 0..3 = S_rr,S_dd,S_ii,S_tt
        w = (i == j) ? 1.0f : 2.0f;  // off-diag tile counted twice by symmetry
    } else {                         // cross pairs (t, m)
        int q = job - 144;
        int p = q / 64;
        int t = q - p * 64;
        pa = 3; pb = p;              // pa = fm_t
        ti = t >> 3; tj = t & 7;
        accIdx = 4 + p;              // 4..6 = S_tr,S_td,S_ti
        w = 1.0f;
    }

    const float* A = g_norm + (size_t)pa * NROWS * DIM + ti * TILE;
    const float* B = g_norm + (size_t)pb * NROWS * DIM + tj * TILE;

    int tid = threadIdx.x;
    int tx = tid & 15;          // output sub-col group
    int ty = tid >> 4;          // output sub-row group
    int lr = tid >> 4;          // load row within BK slab
    int lc = (tid & 15) * 4;    // load col (float4)

    float acc00=0,acc01=0,acc02=0,acc03=0;
    float acc10=0,acc11=0,acc12=0,acc13=0;
    float acc20=0,acc21=0,acc22=0,acc23=0;
    float acc30=0,acc31=0,acc32=0,acc33=0;

    // register prefetch double-buffer
    float4 pva = *(const float4*)(A + (size_t)lr * DIM + lc);
    float4 pvb = *(const float4*)(B + (size_t)lr * DIM + lc);

    for (int k0 = 0; k0 < NROWS; k0 += BK) {
        *(float4*)&As[lr][lc] = pva;
        *(float4*)&Bs[lr][lc] = pvb;
        __syncthreads();
        int kn = k0 + BK;
        if (kn < NROWS) {
            pva = *(const float4*)(A + (size_t)(kn + lr) * DIM + lc);
            pvb = *(const float4*)(B + (size_t)(kn + lr) * DIM + lc);
        }
        #pragma unroll
        for (int kk = 0; kk < BK; kk++) {
            float4 af = *(const float4*)&As[kk][ty * 4];
            float4 bf = *(const float4*)&Bs[kk][tx * 4];
            acc00 += af.x * bf.x; acc01 += af.x * bf.y; acc02 += af.x * bf.z; acc03 += af.x * bf.w;
            acc10 += af.y * bf.x; acc11 += af.y * bf.y; acc12 += af.y * bf.z; acc13 += af.y * bf.w;
            acc20 += af.z * bf.x; acc21 += af.z * bf.y; acc22 += af.z * bf.z; acc23 += af.z * bf.w;
            acc30 += af.w * bf.x; acc31 += af.w * bf.y; acc32 += af.w * bf.z; acc33 += af.w * bf.w;
        }
        __syncthreads();
    }

    // epilogue: sum of squares of this thread's 4x4 fragment
    float s = acc00*acc00 + acc01*acc01 + acc02*acc02 + acc03*acc03
            + acc10*acc10 + acc11*acc11 + acc12*acc12 + acc13*acc13
            + acc20*acc20 + acc21*acc21 + acc22*acc22 + acc23*acc23
            + acc30*acc30 + acc31*acc31 + acc32*acc32 + acc33*acc33;
    #pragma unroll
    for (int o = 16; o > 0; o >>= 1) s += __shfl_xor_sync(0xffffffffu, s, o);
    __shared__ float red[8];
    if ((tid & 31) == 0) red[tid >> 5] = s;
    __syncthreads();
    if (tid < 8) {
        s = red[tid];
        #pragma unroll
        for (int o = 4; o > 0; o >>= 1) s += __shfl_xor_sync(0xffu, s, o);
        if (tid == 0) atomicAdd(&g_acc[accIdx], w * s);
    }
}

__global__ void combine_kernel(float* __restrict__ out) {
    float s_rr = g_acc[0], s_dd = g_acc[1], s_ii = g_acc[2], s_tt = g_acc[3];
    float s_tr = g_acc[4], s_td = g_acc[5], s_ti = g_acc[6];
    // loss = (1/T^2) * (1/N^2) * sum_m [ S_tt - 2 S_tm + S_mm ],  T=0.1 -> *100
    float num = 3.0f * s_tt + s_rr + s_dd + s_ii - 2.0f * (s_tr + s_td + s_ti);
    out[0] = num * (100.0f / 16777216.0f);  // N^2 = 4096^2
}

extern "C" void kernel_launch(void* const* d_in, const int* in_sizes, int n_in,
                              void* d_out, int out_size) {
    const float* rgb   = (const float*)d_in[0];
    const float* depth = (const float*)d_in[1];
    const float* ir    = (const float*)d_in[2];
    const float* tgt   = (const float*)d_in[3];
    float* out = (float*)d_out;

    init_acc_kernel<<<1, 32>>>();
    dim3 ngrid(NROWS, NMOD);
    normalize_kernel<<<ngrid, 128>>>(rgb, depth, ir, tgt);
    gemm_fro_kernel<<<NJOBS, 256>>>();
    combine_kernel<<<1, 1>>>(out);
}

// round 5
// speedup vs baseline: 4.0396x; 4.0396x over previous
#include <cuda_runtime.h>
#include <cuda_bf16.h>
#include <stdint.h>

#define NROWS 4096
#define DIM   512
#define KSTG  64            // K elements per pipeline stage
#define NSTAGES_K (NROWS / KSTG)   // 64
#define ROWPAD 72           // 64 + 8 bf16 pad -> conflict-free LDS
#define STAGE_BYTES (128 * ROWPAD * 2)   // 18432 per operand
#define GEMM_SMEM (3 * 2 * STAGE_BYTES)  // 110592
#define NJOBS 88            // 4 sym pairs * 10 lower-tri tiles + 3 cross * 16

// bf16 normalized + transposed operands: [mod][p=512][r=4096]
__device__ __align__(16) unsigned short g_normT[(size_t)4 * DIM * NROWS];
__device__ float g_acc[7];

// ---------------- helpers ----------------
__device__ __forceinline__ uint32_t smem_u32(const void* p) {
    uint32_t a;
    asm("{ .reg .u64 t; cvta.to.shared.u64 t, %1; cvt.u32.u64 %0, t; }" : "=r"(a) : "l"(p));
    return a;
}
__device__ __forceinline__ void cp_async16(uint32_t s, const void* g) {
    asm volatile("cp.async.cg.shared.global [%0], [%1], 16;" :: "r"(s), "l"(g));
}
__device__ __forceinline__ void cp_commit() {
    asm volatile("cp.async.commit_group;" ::: "memory");
}
template <int N> __device__ __forceinline__ void cp_wait() {
    asm volatile("cp.async.wait_group %0;" :: "n"(N) : "memory");
}
__device__ __forceinline__ void mma_bf16(float* c, const uint32_t* a, const uint32_t* b) {
    asm volatile(
        "mma.sync.aligned.m16n8k16.row.col.f32.bf16.bf16.f32 "
        "{%0,%1,%2,%3}, {%4,%5,%6,%7}, {%8,%9}, {%0,%1,%2,%3};"
        : "+f"(c[0]), "+f"(c[1]), "+f"(c[2]), "+f"(c[3])
        : "r"(a[0]), "r"(a[1]), "r"(a[2]), "r"(a[3]), "r"(b[0]), "r"(b[1]));
}

// ---------------- kernels ----------------
__global__ void init_acc_kernel() {
    if (threadIdx.x < 7) g_acc[threadIdx.x] = 0.0f;
}

// Normalize rows, convert to bf16, write TRANSPOSED: g_normT[m][p][r].
// Block: 32 rows of one modality; 256 threads (8 threads per row).
__global__ __launch_bounds__(256) void norm_t_kernel(const float* __restrict__ in0,
                                                     const float* __restrict__ in1,
                                                     const float* __restrict__ in2,
                                                     const float* __restrict__ in3) {
    __shared__ unsigned short st[32][520];  // [r][p], rows padded to 16B multiple
    int m = blockIdx.y;
    int r0 = blockIdx.x * 32;
    const float* src = (m == 0 ? in0 : m == 1 ? in1 : m == 2 ? in2 : in3);

    int t = threadIdx.x;
    int rl = t >> 3;        // local row 0..31
    int q  = t & 7;         // 64-col segment
    const float4* rp = (const float4*)(src + ((size_t)(r0 + rl)) * DIM + q * 64);

    float4 v[16];
    float ss = 0.0f;
    #pragma unroll
    for (int j = 0; j < 16; j++) {
        v[j] = rp[j];
        ss += v[j].x * v[j].x + v[j].y * v[j].y + v[j].z * v[j].z + v[j].w * v[j].w;
    }
    #pragma unroll
    for (int o = 4; o > 0; o >>= 1) ss += __shfl_xor_sync(0xffffffffu, ss, o);
    float inv = 1.0f / fmaxf(sqrtf(ss), 1e-12f);

    unsigned short* dstp = &st[rl][q * 64];
    #pragma unroll
    for (int j = 0; j < 16; j++) {
        unsigned short ax = __bfloat16_as_ushort(__float2bfloat16(v[j].x * inv));
        unsigned short ay = __bfloat16_as_ushort(__float2bfloat16(v[j].y * inv));
        unsigned short az = __bfloat16_as_ushort(__float2bfloat16(v[j].z * inv));
        unsigned short aw = __bfloat16_as_ushort(__float2bfloat16(v[j].w * inv));
        uint32_t lo = (uint32_t)ax | ((uint32_t)ay << 16);
        uint32_t hi = (uint32_t)az | ((uint32_t)aw << 16);
        *(uint2*)(dstp + j * 4) = make_uint2(lo, hi);
    }
    __syncthreads();

    // Transposed write: for each feature p, pack this block's 32 r-values.
    #pragma unroll
    for (int it = 0; it < 8; it++) {
        int task = t + it * 256;      // 0..2047 = 512 p * 4 chunks
        int p = task >> 2;
        int rb = (task & 3) * 8;
        uint32_t w0 = (uint32_t)st[rb + 0][p] | ((uint32_t)st[rb + 1][p] << 16);
        uint32_t w1 = (uint32_t)st[rb + 2][p] | ((uint32_t)st[rb + 3][p] << 16);
        uint32_t w2 = (uint32_t)st[rb + 4][p] | ((uint32_t)st[rb + 5][p] << 16);
        uint32_t w3 = (uint32_t)st[rb + 6][p] | ((uint32_t)st[rb + 7][p] << 16);
        size_t off = ((size_t)m * DIM + p) * NROWS + r0 + rb;
        *(uint4*)((char*)g_normT + off * 2) = make_uint4(w0, w1, w2, w3);
    }
}

// One 128x128 tile of C = N_a^T N_b via mma.sync bf16 (HMMA), cp.async 3-stage
// pipeline, fused Frobenius sum-of-squares epilogue from registers.
__global__ __launch_bounds__(256, 1) void gemm_mma_kernel() {
    extern __shared__ char dsm[];

    int tid  = threadIdx.x;
    int wid  = tid >> 5;
    int lane = tid & 31;
    int wm   = wid & 1;     // warp row  (2)
    int wn   = wid >> 1;    // warp col  (4)
    int qrow = lane >> 2;   // 0..7
    int qk   = (lane & 3) * 2;

    // ---- job decode ----
    int job = blockIdx.x;
    int pa, pb, ti, tj, accIdx;
    float wgt;
    if (job < 40) {                 // symmetric pairs, lower triangle of 4x4 tiles
        int p = job / 10;
        int t = job - p * 10;
        int i = 0;
        while (((i + 1) * (i + 2)) / 2 <= t) i++;
        int j = t - (i * (i + 1)) / 2;
        pa = p; pb = p; ti = i; tj = j;
        accIdx = p;
        wgt = (i == j) ? 1.0f : 2.0f;
    } else {                        // cross pairs (t, m)
        int q = job - 40;
        int p = q >> 4;
        int t = q & 15;
        pa = 3; pb = p;
        ti = t >> 2; tj = t & 3;
        accIdx = 4 + p;
        wgt = 1.0f;
    }

    const char* Abase = (const char*)g_normT + ((size_t)(pa * DIM + ti * 128)) * NROWS * 2;
    const char* Bbase = (const char*)g_normT + ((size_t)(pb * DIM + tj * 128)) * NROWS * 2;
    uint32_t sbase = smem_u32(dsm);

    // ---- cp.async issue for stage s ----
    auto issue = [&](int s) {
        uint32_t buf = sbase + (uint32_t)(s % 3) * (2 * STAGE_BYTES);
        size_t gk = (size_t)s * KSTG * 2;  // byte offset along a K-row
        #pragma unroll
        for (int it = 0; it < 8; it++) {
            int task = tid + it * 256;     // 0..2047
            int isB  = task >> 10;
            int lt   = task & 1023;
            int row  = lt >> 3;            // 0..127
            int c    = lt & 7;             // 16B chunk within 128B of K
            const char* g = (isB ? Bbase : Abase) + (size_t)row * (NROWS * 2) + gk + c * 16;
            uint32_t sa = buf + (isB ? STAGE_BYTES : 0u)
                        + (uint32_t)(row * (ROWPAD * 2) + c * 16);
            cp_async16(sa, g);
        }
        cp_commit();
    };

    float acc[4][4][4];
    #pragma unroll
    for (int im = 0; im < 4; im++)
        #pragma unroll
        for (int in = 0; in < 4; in++)
            #pragma unroll
            for (int e = 0; e < 4; e++) acc[im][in][e] = 0.0f;

    issue(0);
    issue(1);

    for (int s = 0; s < NSTAGES_K; s++) {
        if (s == NSTAGES_K - 1) cp_wait<0>(); else cp_wait<1>();
        __syncthreads();

        const unsigned short* Abuf =
            (const unsigned short*)(dsm + (s % 3) * (2 * STAGE_BYTES));
        const unsigned short* Bbuf = Abuf + STAGE_BYTES / 2;

        #pragma unroll
        for (int kk = 0; kk < 4; kk++) {       // 4 x k16 within the stage
            int kb = kk * 16 + qk;
            uint32_t a[4][4], b[4][2];
            #pragma unroll
            for (int im = 0; im < 4; im++) {
                const unsigned short* ap =
                    Abuf + (wm * 64 + im * 16 + qrow) * ROWPAD + kb;
                a[im][0] = *(const uint32_t*)(ap);
                a[im][1] = *(const uint32_t*)(ap + 8 * ROWPAD);
                a[im][2] = *(const uint32_t*)(ap + 8);
                a[im][3] = *(const uint32_t*)(ap + 8 * ROWPAD + 8);
            }
            #pragma unroll
            for (int in = 0; in < 4; in++) {
                const unsigned short* bp =
                    Bbuf + (wn * 32 + in * 8 + qrow) * ROWPAD + kb;
                b[in][0] = *(const uint32_t*)(bp);
                b[in][1] = *(const uint32_t*)(bp + 8);
            }
            #pragma unroll
            for (int im = 0; im < 4; im++)
                #pragma unroll
                for (int in = 0; in < 4; in++)
                    mma_bf16(acc[im][in], a[im], b[in]);
        }
        __syncthreads();
        if (s + 2 < NSTAGES_K) issue(s + 2);
    }

    // ---- epilogue: Frobenius sum of squares from registers ----
    float ssum = 0.0f;
    #pragma unroll
    for (int im = 0; im < 4; im++)
        #pragma unroll
        for (int in = 0; in < 4; in++)
            #pragma unroll
            for (int e = 0; e < 4; e++) {
                float f = acc[im][in][e];
                ssum += f * f;
            }
    #pragma unroll
    for (int o = 16; o > 0; o >>= 1) ssum += __shfl_xor_sync(0xffffffffu, ssum, o);
    __shared__ float red[8];
    if (lane == 0) red[wid] = ssum;
    __syncthreads();
    if (tid == 0) {
        float s8 = red[0] + red[1] + red[2] + red[3]
                 + red[4] + red[5] + red[6] + red[7];
        atomicAdd(&g_acc[accIdx], wgt * s8);
    }
}

__global__ void combine_kernel(float* __restrict__ out) {
    float s_rr = g_acc[0], s_dd = g_acc[1], s_ii = g_acc[2], s_tt = g_acc[3];
    float s_tr = g_acc[4], s_td = g_acc[5], s_ti = g_acc[6];
    float num = 3.0f * s_tt + s_rr + s_dd + s_ii - 2.0f * (s_tr + s_td + s_ti);
    out[0] = num * (100.0f / 16777216.0f);  // (1/T^2) / N^2
}

extern "C" void kernel_launch(void* const* d_in, const int* in_sizes, int n_in,
                              void* d_out, int out_size) {
    const float* rgb   = (const float*)d_in[0];
    const float* depth = (const float*)d_in[1];
    const float* ir    = (const float*)d_in[2];
    const float* tgt   = (const float*)d_in[3];
    float* out = (float*)d_out;

    cudaFuncSetAttribute(gemm_mma_kernel, cudaFuncAttributeMaxDynamicSharedMemorySize,
                         GEMM_SMEM);

    init_acc_kernel<<<1, 32>>>();
    dim3 ngrid(NROWS / 32, 4);
    norm_t_kernel<<<ngrid, 256>>>(rgb, depth, ir, tgt);
    gemm_mma_kernel<<<NJOBS, 256, GEMM_SMEM>>>();
    combine_kernel<<<1, 1>>>(out);
}

// round 7
// speedup vs baseline: 4.5383x; 1.1235x over previous
#include <cuda_runtime.h>
#include <cuda_bf16.h>
#include <stdint.h>

#define NROWS 4096
#define DIM   512
#define KSTG  64                         // K elements per pipeline stage
#define NSTAGES_K (NROWS / KSTG)         // 64
#define ROWPAD 72                        // 64 + 8 bf16 pad -> conflict-free smem
#define STAGE_BYTES (128 * ROWPAD * 2)   // 18432 per operand
#define GEMM_SMEM (3 * 2 * STAGE_BYTES)  // 110592
#define NJOBS 88                         // 4 sym * 10 lower-tri + 3 cross * 16

// bf16 normalized + transposed operands: [mod][p=512][r=4096]
__device__ __align__(16) unsigned short g_normT[(size_t)4 * DIM * NROWS];
__device__ float g_acc[7];
__device__ int g_cnt;

// ---------------- helpers ----------------
__device__ __forceinline__ uint32_t smem_u32(const void* p) {
    uint32_t a;
    asm("{ .reg .u64 t; cvta.to.shared.u64 t, %1; cvt.u32.u64 %0, t; }" : "=r"(a) : "l"(p));
    return a;
}
__device__ __forceinline__ void cp_async16(uint32_t s, const void* g) {
    asm volatile("cp.async.cg.shared.global [%0], [%1], 16;" :: "r"(s), "l"(g));
}
__device__ __forceinline__ void cp_commit() {
    asm volatile("cp.async.commit_group;" ::: "memory");
}
template <int N> __device__ __forceinline__ void cp_wait() {
    asm volatile("cp.async.wait_group %0;" :: "n"(N) : "memory");
}
__device__ __forceinline__ void mma_bf16(float* c, const uint32_t* a, const uint32_t* b) {
    asm volatile(
        "mma.sync.aligned.m16n8k16.row.col.f32.bf16.bf16.f32 "
        "{%0,%1,%2,%3}, {%4,%5,%6,%7}, {%8,%9}, {%0,%1,%2,%3};"
        : "+f"(c[0]), "+f"(c[1]), "+f"(c[2]), "+f"(c[3])
        : "r"(a[0]), "r"(a[1]), "r"(a[2]), "r"(a[3]), "r"(b[0]), "r"(b[1]));
}
__device__ __forceinline__ void ldsm_x4(uint32_t* r, uint32_t a) {
    asm volatile("ldmatrix.sync.aligned.m8n8.x4.shared.b16 {%0,%1,%2,%3}, [%4];"
        : "=r"(r[0]), "=r"(r[1]), "=r"(r[2]), "=r"(r[3]) : "r"(a));
}
__device__ __forceinline__ void ldsm_x2(uint32_t* r, uint32_t a) {
    asm volatile("ldmatrix.sync.aligned.m8n8.x2.shared.b16 {%0,%1}, [%2];"
        : "=r"(r[0]), "=r"(r[1]) : "r"(a));
}

// ---------------- kernels ----------------

// Normalize rows, convert to bf16, write TRANSPOSED: g_normT[m][p][r].
// Block: 32 rows of one modality; 256 threads (8 per row).
// Block (0,0) also zero-inits the accumulators + ticket counter (runs before gemm).
__global__ __launch_bounds__(256) void norm_t_kernel(const float* __restrict__ in0,
                                                     const float* __restrict__ in1,
                                                     const float* __restrict__ in2,
                                                     const float* __restrict__ in3) {
    __shared__ unsigned short st[32][520];  // [r][p], rows padded to 16B multiple
    int m = blockIdx.y;
    int r0 = blockIdx.x * 32;
    const float* src = (m == 0 ? in0 : m == 1 ? in1 : m == 2 ? in2 : in3);

    int t = threadIdx.x;
    if (blockIdx.x == 0 && m == 0 && t < 8) {
        if (t < 7) g_acc[t] = 0.0f;
        else g_cnt = 0;
    }

    int rl = t >> 3;        // local row 0..31
    int q  = t & 7;         // 64-col segment
    const float4* rp = (const float4*)(src + ((size_t)(r0 + rl)) * DIM + q * 64);

    float4 v[16];
    float ss = 0.0f;
    #pragma unroll
    for (int j = 0; j < 16; j++) {
        v[j] = rp[j];
        ss += v[j].x * v[j].x + v[j].y * v[j].y + v[j].z * v[j].z + v[j].w * v[j].w;
    }
    #pragma unroll
    for (int o = 4; o > 0; o >>= 1) ss += __shfl_xor_sync(0xffffffffu, ss, o);
    float inv = 1.0f / fmaxf(sqrtf(ss), 1e-12f);

    unsigned short* dstp = &st[rl][q * 64];
    #pragma unroll
    for (int j = 0; j < 16; j++) {
        unsigned short ax = __bfloat16_as_ushort(__float2bfloat16(v[j].x * inv));
        unsigned short ay = __bfloat16_as_ushort(__float2bfloat16(v[j].y * inv));
        unsigned short az = __bfloat16_as_ushort(__float2bfloat16(v[j].z * inv));
        unsigned short aw = __bfloat16_as_ushort(__float2bfloat16(v[j].w * inv));
        uint32_t lo = (uint32_t)ax | ((uint32_t)ay << 16);
        uint32_t hi = (uint32_t)az | ((uint32_t)aw << 16);
        *(uint2*)(dstp + j * 4) = make_uint2(lo, hi);
    }
    __syncthreads();

    // Transposed write: for each feature p, pack this block's 32 r-values.
    #pragma unroll
    for (int it = 0; it < 8; it++) {
        int task = t + it * 256;      // 0..2047 = 512 p * 4 chunks
        int p = task >> 2;
        int rb = (task & 3) * 8;
        uint32_t w0 = (uint32_t)st[rb + 0][p] | ((uint32_t)st[rb + 1][p] << 16);
        uint32_t w1 = (uint32_t)st[rb + 2][p] | ((uint32_t)st[rb + 3][p] << 16);
        uint32_t w2 = (uint32_t)st[rb + 4][p] | ((uint32_t)st[rb + 5][p] << 16);
        uint32_t w3 = (uint32_t)st[rb + 6][p] | ((uint32_t)st[rb + 7][p] << 16);
        size_t off = ((size_t)m * DIM + p) * NROWS + r0 + rb;
        *(uint4*)((char*)g_normT + off * 2) = make_uint4(w0, w1, w2, w3);
    }
}

// One 128x128 tile of C = N_a^T N_b via mma.sync bf16, ldmatrix fragment loads,
// 3-stage cp.async pipeline, register-resident Frobenius epilogue; last CTA
// combines the 7 partial sums into the final loss.
__global__ __launch_bounds__(256, 1) void gemm_mma_kernel(float* __restrict__ out) {
    extern __shared__ char dsm[];

    int tid  = threadIdx.x;
    int wid  = tid >> 5;
    int lane = tid & 31;
    int wm   = wid & 1;     // warp row  (2)
    int wn   = wid >> 1;    // warp col  (4)

    // ---- job decode ----
    int job = blockIdx.x;
    int pa, pb, ti, tj, accIdx;
    float wgt;
    if (job < 40) {                 // symmetric pairs, lower triangle of 4x4 tiles
        int p = job / 10;
        int t = job - p * 10;
        int i = 0;
        while (((i + 1) * (i + 2)) / 2 <= t) i++;
        int j = t - (i * (i + 1)) / 2;
        pa = p; pb = p; ti = i; tj = j;
        accIdx = p;
        wgt = (i == j) ? 1.0f : 2.0f;
    } else {                        // cross pairs (t, m)
        int q = job - 40;
        int p = q >> 4;
        int t = q & 15;
        pa = 3; pb = p;
        ti = t >> 2; tj = t & 3;
        accIdx = 4 + p;
        wgt = 1.0f;
    }

    const char* Abase = (const char*)g_normT + ((size_t)(pa * DIM + ti * 128)) * NROWS * 2;
    const char* Bbase = (const char*)g_normT + ((size_t)(pb * DIM + tj * 128)) * NROWS * 2;
    uint32_t sbase = smem_u32(dsm);

    // ldmatrix per-lane relative byte offsets within a stage buffer
    uint32_t aRel[4], bRel[4];
    {
        uint32_t arow = (lane & 7) + 8 * ((lane >> 3) & 1);
        uint32_t akh  = ((lane >> 4) & 1) * 16;           // k-half 16B
        uint32_t brow = lane & 7;
        uint32_t bkh  = ((lane >> 3) & 1) * 16;
        #pragma unroll
        for (int im = 0; im < 4; im++)
            aRel[im] = (wm * 64 + im * 16 + arow) * (ROWPAD * 2) + akh;
        #pragma unroll
        for (int in = 0; in < 4; in++)
            bRel[in] = (wn * 32 + in * 8 + brow) * (ROWPAD * 2) + bkh;
    }

    // ---- cp.async issue for stage s ----
    auto issue = [&](int s) {
        uint32_t buf = sbase + (uint32_t)(s % 3) * (2 * STAGE_BYTES);
        size_t gk = (size_t)s * KSTG * 2;  // byte offset along a K-row
        #pragma unroll
        for (int it = 0; it < 8; it++) {
            int task = tid + it * 256;     // 0..2047
            int isB  = task >> 10;
            int lt   = task & 1023;
            int row  = lt >> 3;            // 0..127
            int c    = lt & 7;             // 16B chunk within 128B of K
            const char* g = (isB ? Bbase : Abase) + (size_t)row * (NROWS * 2) + gk + c * 16;
            uint32_t sa = buf + (isB ? STAGE_BYTES : 0u)
                        + (uint32_t)(row * (ROWPAD * 2) + c * 16);
            cp_async16(sa, g);
        }
        cp_commit();
    };

    float acc[4][4][4];
    #pragma unroll
    for (int im = 0; im < 4; im++)
        #pragma unroll
        for (int in = 0; in < 4; in++)
            #pragma unroll
            for (int e = 0; e < 4; e++) acc[im][in][e] = 0.0f;

    issue(0);
    issue(1);

    for (int s = 0; s < NSTAGES_K; s++) {
        if (s == NSTAGES_K - 1) cp_wait<0>(); else cp_wait<1>();
        __syncthreads();

        uint32_t bufA = sbase + (uint32_t)(s % 3) * (2 * STAGE_BYTES);
        uint32_t bufB = bufA + STAGE_BYTES;

        #pragma unroll
        for (int kk = 0; kk < 4; kk++) {       // 4 x k16 within the stage
            uint32_t a[4][4], b[4][2];
            #pragma unroll
            for (int im = 0; im < 4; im++) ldsm_x4(a[im], bufA + aRel[im] + kk * 32);
            #pragma unroll
            for (int in = 0; in < 4; in++) ldsm_x2(b[in], bufB + bRel[in] + kk * 32);
            #pragma unroll
            for (int im = 0; im < 4; im++)
                #pragma unroll
                for (int in = 0; in < 4; in++)
                    mma_bf16(acc[im][in], a[im], b[in]);
        }
        // No second barrier: the next iteration's post-wait __syncthreads already
        // proves all warps finished reading the buffer that issue(s+2) overwrites.
        if (s + 2 < NSTAGES_K) issue(s + 2);
    }

    // ---- epilogue: Frobenius sum of squares from registers ----
    float ssum = 0.0f;
    #pragma unroll
    for (int im = 0; im < 4; im++)
        #pragma unroll
        for (int in = 0; in < 4; in++)
            #pragma unroll
            for (int e = 0; e < 4; e++) {
                float f = acc[im][in][e];
                ssum += f * f;
            }
    #pragma unroll
    for (int o = 16; o > 0; o >>= 1) ssum += __shfl_xor_sync(0xffffffffu, ssum, o);
    __shared__ float red[8];
    if (lane == 0) red[wid] = ssum;
    __syncthreads();
    if (tid == 0) {
        float s8 = red[0] + red[1] + red[2] + red[3]
                 + red[4] + red[5] + red[6] + red[7];
        atomicAdd(&g_acc[accIdx], wgt * s8);
        __threadfence();
        int done = atomicAdd(&g_cnt, 1);
        if (done == NJOBS - 1) {
            // all CTAs' g_acc contributions are visible (fence + atomic order)
            volatile float* ga = g_acc;
            float s_rr = ga[0], s_dd = ga[1], s_ii = ga[2], s_tt = ga[3];
            float s_tr = ga[4], s_td = ga[5], s_ti = ga[6];
            float num = 3.0f * s_tt + s_rr + s_dd + s_ii
                      - 2.0f * (s_tr + s_td + s_ti);
            out[0] = num * (100.0f / 16777216.0f);  // (1/T^2) / N^2
        }
    }
}

extern "C" void kernel_launch(void* const* d_in, const int* in_sizes, int n_in,
                              void* d_out, int out_size) {
    const float* rgb   = (const float*)d_in[0];
    const float* depth = (const float*)d_in[1];
    const float* ir    = (const float*)d_in[2];
    const float* tgt   = (const float*)d_in[3];
    float* out = (float*)d_out;

    cudaFuncSetAttribute(gemm_mma_kernel, cudaFuncAttributeMaxDynamicSharedMemorySize,
                         GEMM_SMEM);

    dim3 ngrid(NROWS / 32, 4);
    norm_t_kernel<<<ngrid, 256>>>(rgb, depth, ir, tgt);
    gemm_mma_kernel<<<NJOBS, 256, GEMM_SMEM>>>(out);
}